// round 2
// baseline (speedup 1.0000x reference)
#include <cuda_runtime.h>

#define N_NODES 50000
#define N_EDGES 1600000
#define HID 256

// ---------------- device scratch (static, no allocs) ----------------
__device__ float4 g_hb [N_NODES*HID/4];   // h buffer A (relu'd layer outputs)
__device__ float4 g_hnb[N_NODES*HID/4];   // h buffer B
__device__ float4 g_agb[N_NODES*HID/4];   // aggregation buffer
__device__ int    g_src[N_EDGES];
__device__ int    g_dst[N_EDGES];
__device__ int    g_flag;                 // 1 = edge_index is int64, 0 = int32

// ---------------- vector reductions (sm_90+) ----------------
__device__ __forceinline__ void red_add_v4(float* a, float4 v) {
    asm volatile("red.global.add.v4.f32 [%0], {%1,%2,%3,%4};"
                 :: "l"(a), "f"(v.x), "f"(v.y), "f"(v.z), "f"(v.w) : "memory");
}
__device__ __forceinline__ void red_add_v2(float* a, float x, float y) {
    asm volatile("red.global.add.v2.f32 [%0], {%1,%2};"
                 :: "l"(a), "f"(x), "f"(y) : "memory");
}

// ---------------- dtype detection ----------------
__global__ void k_detect(const void* ei) {
    if (threadIdx.x == 0) {
        const long long* p = (const long long*)ei;
        int is64 = 1;
        for (int i = 0; i < 64; i++) {
            long long v = p[i];
            if (v < 0 || v >= N_NODES) { is64 = 0; break; }
        }
        g_flag = is64;
    }
}

__global__ void k_convert(const void* ei) {
    int i = blockIdx.x * blockDim.x + threadIdx.x;
    if (i >= N_EDGES) return;
    if (g_flag) {
        const long long* p = (const long long*)ei;
        g_src[i] = (int)p[i];
        g_dst[i] = (int)p[N_EDGES + i];
    } else {
        const int* p = (const int*)ei;
        g_src[i] = p[i];
        g_dst[i] = p[N_EDGES + i];
    }
}

// ---------------- zero the aggregation buffer ----------------
__global__ void k_zero(int n4) {
    float4 z = make_float4(0.f, 0.f, 0.f, 0.f);
    for (int i = blockIdx.x * blockDim.x + threadIdx.x; i < n4;
         i += gridDim.x * blockDim.x)
        g_agb[i] = z;
}

// ---------------- layer 1 scatter (C = 2) ----------------
__global__ void k_scatter1(const float* __restrict__ x,
                           const float* __restrict__ ea,
                           const float* __restrict__ We1,
                           const float* __restrict__ be1) {
    int e = blockIdx.x * blockDim.x + threadIdx.x;
    if (e >= N_EDGES) return;
    float a[7];
#pragma unroll
    for (int k = 0; k < 7; k++) a[k] = ea[e * 7 + k];
    float e0 = __ldg(&be1[0]), e1 = __ldg(&be1[1]);
#pragma unroll
    for (int k = 0; k < 7; k++) {
        e0 += a[k] * __ldg(&We1[k * 2 + 0]);
        e1 += a[k] * __ldg(&We1[k * 2 + 1]);
    }
    int s = g_src[e], d = g_dst[e];
    float m0 = fmaxf(x[2 * s + 0] + e0, 0.f);
    float m1 = fmaxf(x[2 * s + 1] + e1, 0.f);
    red_add_v2(((float*)g_agb) + 2 * d, m0, m1);
}

// ---------------- layer 1 nn: h = relu((x + aggr) @ W1 + b1) ----------------
__global__ void k_layer1nn(const float* __restrict__ x,
                           const float* __restrict__ W1,
                           const float* __restrict__ b1) {
    int n = blockIdx.x;
    int c = threadIdx.x;
    const float* ag = (const float*)g_agb;
    float a0 = x[2 * n + 0] + ag[2 * n + 0];
    float a1 = x[2 * n + 1] + ag[2 * n + 1];
    float v = b1[c] + a0 * W1[c] + a1 * W1[HID + c];
    ((float*)g_hb)[n * HID + c] = fmaxf(v, 0.f);
}

// ---------------- layers 2/3 scatter: warp per edge, weights in registers ---
__global__ void __launch_bounds__(256, 2)
k_scatter2(int useHn, const float* __restrict__ ea,
           const float* __restrict__ We2, const float* __restrict__ be2) {
    const float* hin = useHn ? (const float*)g_hnb : (const float*)g_hb;
    float* aggr = (float*)g_agb;
    int lane = threadIdx.x & 31;
    int gw = (blockIdx.x * blockDim.x + threadIdx.x) >> 5;
    int nw = (gridDim.x * blockDim.x) >> 5;
    int chA = lane * 4;
    int chB = 128 + lane * 4;

    // per-lane fixed channel weights live in registers for the whole loop
    float4 wA[7], wB[7];
#pragma unroll
    for (int k = 0; k < 7; k++) {
        wA[k] = *(const float4*)&We2[k * HID + chA];
        wB[k] = *(const float4*)&We2[k * HID + chB];
    }
    float4 bA = *(const float4*)&be2[chA];
    float4 bB = *(const float4*)&be2[chB];

    for (int e = gw; e < N_EDGES; e += nw) {
        float a[7];
#pragma unroll
        for (int k = 0; k < 7; k++) a[k] = __ldg(&ea[e * 7 + k]);
        int s = g_src[e], d = g_dst[e];
        float4 hA = *(const float4*)&hin[s * HID + chA];
        float4 hB = *(const float4*)&hin[s * HID + chB];
        float4 mA = bA, mB = bB;
#pragma unroll
        for (int k = 0; k < 7; k++) {
            mA.x += a[k] * wA[k].x; mA.y += a[k] * wA[k].y;
            mA.z += a[k] * wA[k].z; mA.w += a[k] * wA[k].w;
            mB.x += a[k] * wB[k].x; mB.y += a[k] * wB[k].y;
            mB.z += a[k] * wB[k].z; mB.w += a[k] * wB[k].w;
        }
        mA.x = fmaxf(mA.x + hA.x, 0.f); mA.y = fmaxf(mA.y + hA.y, 0.f);
        mA.z = fmaxf(mA.z + hA.z, 0.f); mA.w = fmaxf(mA.w + hA.w, 0.f);
        mB.x = fmaxf(mB.x + hB.x, 0.f); mB.y = fmaxf(mB.y + hB.y, 0.f);
        mB.z = fmaxf(mB.z + hB.z, 0.f); mB.w = fmaxf(mB.w + hB.w, 0.f);
        red_add_v4(aggr + d * HID + chA, mA);
        red_add_v4(aggr + d * HID + chB, mB);
    }
}

// ---------------- GEMM: hout = relu((hin + aggr) @ W + b) ----------------
// M=50000, N=256, K=256.  BM=64, BN=64, BK=16, 256 threads, 4x4 per thread.
__global__ void __launch_bounds__(256)
k_gemm_relu(int useHn, const float* __restrict__ W, const float* __restrict__ b) {
    const float* hin = useHn ? (const float*)g_hnb : (const float*)g_hb;
    float* hout      = useHn ? (float*)g_hb       : (float*)g_hnb;
    const float* ag  = (const float*)g_agb;

    __shared__ float As[64][17];
    __shared__ float Bs[16][64];

    int tid = threadIdx.x;
    int tx = tid & 15, ty = tid >> 4;
    int rowBase = blockIdx.y * 64;
    int colBase = blockIdx.x * 64;

    float acc[4][4];
#pragma unroll
    for (int i = 0; i < 4; i++)
#pragma unroll
        for (int j = 0; j < 4; j++) acc[i][j] = 0.f;

    for (int kt = 0; kt < HID; kt += 16) {
#pragma unroll
        for (int i = 0; i < 4; i++) {
            int idx = tid * 4 + i;
            int r = idx >> 4, c = idx & 15;
            int grow = rowBase + r;
            float v = 0.f;
            if (grow < N_NODES) {
                int gi = grow * HID + kt + c;
                v = hin[gi] + ag[gi];
            }
            As[r][c] = v;
        }
#pragma unroll
        for (int i = 0; i < 4; i++) {
            int idx = tid * 4 + i;
            int r = idx >> 6, c = idx & 63;
            Bs[r][c] = W[(kt + r) * HID + colBase + c];
        }
        __syncthreads();
#pragma unroll
        for (int k = 0; k < 16; k++) {
            float av[4], bv[4];
#pragma unroll
            for (int i = 0; i < 4; i++) av[i] = As[ty * 4 + i][k];
#pragma unroll
            for (int j = 0; j < 4; j++) bv[j] = Bs[k][tx * 4 + j];
#pragma unroll
            for (int i = 0; i < 4; i++)
#pragma unroll
                for (int j = 0; j < 4; j++) acc[i][j] += av[i] * bv[j];
        }
        __syncthreads();
    }

#pragma unroll
    for (int i = 0; i < 4; i++) {
        int grow = rowBase + ty * 4 + i;
        if (grow >= N_NODES) continue;
#pragma unroll
        for (int j = 0; j < 4; j++) {
            int col = colBase + tx * 4 + j;
            hout[grow * HID + col] = fmaxf(acc[i][j] + b[col], 0.f);
        }
    }
}

// ---------------- final: sigmoid(h @ Wend + bend) ----------------
__global__ void k_final(const float* __restrict__ Wend,
                        const float* __restrict__ bend,
                        float* __restrict__ out) {
    int lane = threadIdx.x & 31;
    int warp = threadIdx.x >> 5;
    int n = blockIdx.x * 8 + warp;
    if (n >= N_NODES) return;
    const float* h = (const float*)g_hb;
    float s = 0.f;
#pragma unroll
    for (int c = lane * 4; c < HID; c += 128) {
        float4 hv = *(const float4*)&h[n * HID + c];
        float4 wv = *(const float4*)&Wend[c];
        s += hv.x * wv.x + hv.y * wv.y + hv.z * wv.z + hv.w * wv.w;
    }
#pragma unroll
    for (int o = 16; o; o >>= 1) s += __shfl_xor_sync(0xffffffffu, s, o);
    if (lane == 0) out[n] = 1.f / (1.f + __expf(-(s + bend[0])));
}

// ---------------- host ----------------
extern "C" void kernel_launch(void* const* d_in, const int* in_sizes, int n_in,
                              void* d_out, int out_size) {
    const float* x    = (const float*)d_in[0];
    const void*  ei   = d_in[1];
    const float* ea   = (const float*)d_in[2];
    const float* We1  = (const float*)d_in[3];
    const float* be1  = (const float*)d_in[4];
    const float* W1   = (const float*)d_in[5];
    const float* b1   = (const float*)d_in[6];
    const float* We2  = (const float*)d_in[7];
    const float* be2  = (const float*)d_in[8];
    const float* W2   = (const float*)d_in[9];
    const float* b2   = (const float*)d_in[10];
    const float* Wend = (const float*)d_in[11];
    const float* bend = (const float*)d_in[12];
    float* out = (float*)d_out;

    k_detect<<<1, 32>>>(ei);
    k_convert<<<(N_EDGES + 255) / 256, 256>>>(ei);

    // layer 1
    k_zero<<<128, 256>>>(N_NODES * 2 / 4);
    k_scatter1<<<(N_EDGES + 255) / 256, 256>>>(x, ea, We1, be1);
    k_layer1nn<<<N_NODES, 256>>>(x, W1, b1);

    // layer 2 (hin = g_hb, hout = g_hnb)
    k_zero<<<2048, 256>>>(N_NODES * HID / 4);
    k_scatter2<<<1184, 256>>>(0, ea, We2, be2);
    k_gemm_relu<<<dim3(4, 782), 256>>>(0, W2, b2);

    // layer 3 (hin = g_hnb, hout = g_hb)
    k_zero<<<2048, 256>>>(N_NODES * HID / 4);
    k_scatter2<<<1184, 256>>>(1, ea, We2, be2);
    k_gemm_relu<<<dim3(4, 782), 256>>>(1, W2, b2);

    k_final<<<(N_NODES + 7) / 8, 256>>>(Wend, bend, out);
}

// round 3
// speedup vs baseline: 1.0953x; 1.0953x over previous
#include <cuda_runtime.h>

#define N_NODES 50000
#define N_EDGES 1600000
#define HID 256

// ---------------- device scratch (static, no allocs) ----------------
__device__ float4 g_hb [N_NODES*HID/4];   // h buffer A
__device__ float4 g_hnb[N_NODES*HID/4];   // h buffer B
__device__ float4 g_agb[N_NODES*HID/4];   // (h_self + aggr) buffer / layer1 aggr
__device__ int    g_src[N_EDGES];
__device__ int    g_dst[N_EDGES];
__device__ int    g_deg[N_NODES];
__device__ int    g_rowptr[N_NODES + 1];
__device__ int    g_cur[N_NODES];
__device__ int2   g_csr[N_EDGES];         // (src, edge_id) grouped by dst
__device__ int    g_flag;                 // 1 = edge_index int64, 0 = int32

__device__ __forceinline__ void red_add_v2(float* a, float x, float y) {
    asm volatile("red.global.add.v2.f32 [%0], {%1,%2};"
                 :: "l"(a), "f"(x), "f"(y) : "memory");
}

// ---------------- dtype detection + index conversion ----------------
__global__ void k_detect(const void* ei) {
    if (threadIdx.x == 0) {
        const long long* p = (const long long*)ei;
        int is64 = 1;
        for (int i = 0; i < 64; i++) {
            long long v = p[i];
            if (v < 0 || v >= N_NODES) { is64 = 0; break; }
        }
        g_flag = is64;
    }
}

__global__ void k_convert(const void* ei) {
    int i = blockIdx.x * blockDim.x + threadIdx.x;
    if (i >= N_EDGES) return;
    if (g_flag) {
        const long long* p = (const long long*)ei;
        g_src[i] = (int)p[i];
        g_dst[i] = (int)p[N_EDGES + i];
    } else {
        const int* p = (const int*)ei;
        g_src[i] = p[i];
        g_dst[i] = p[N_EDGES + i];
    }
}

// ---------------- CSR build ----------------
__global__ void k_hist() {
    int i = blockIdx.x * blockDim.x + threadIdx.x;
    if (i < N_EDGES) atomicAdd(&g_deg[g_dst[i]], 1);
}

__global__ void k_scan() {   // single block, 1024 threads
    __shared__ int sm[1024];
    int t = threadIdx.x;
    const int CH = (N_NODES + 1023) / 1024;   // 49
    int base = t * CH;
    int s = 0;
    for (int i = 0; i < CH; i++) {
        int n = base + i;
        if (n < N_NODES) s += g_deg[n];
    }
    sm[t] = s;
    __syncthreads();
    for (int o = 1; o < 1024; o <<= 1) {
        int u = (t >= o) ? sm[t - o] : 0;
        __syncthreads();
        sm[t] += u;
        __syncthreads();
    }
    int run = sm[t] - s;   // exclusive prefix
    for (int i = 0; i < CH; i++) {
        int n = base + i;
        if (n < N_NODES) {
            g_rowptr[n] = run;
            g_cur[n] = run;
            run += g_deg[n];
        }
    }
    if (t == 1023) g_rowptr[N_NODES] = N_EDGES;
}

__global__ void k_fill() {
    int e = blockIdx.x * blockDim.x + threadIdx.x;
    if (e >= N_EDGES) return;
    int d = g_dst[e];
    int pos = atomicAdd(&g_cur[d], 1);
    g_csr[pos] = make_int2(g_src[e], e);
}

// ---------------- layer 1 scatter (C = 2, atomic push) ----------------
__global__ void k_scatter1(const float* __restrict__ x,
                           const float* __restrict__ ea,
                           const float* __restrict__ We1,
                           const float* __restrict__ be1) {
    int e = blockIdx.x * blockDim.x + threadIdx.x;
    if (e >= N_EDGES) return;
    float a[7];
#pragma unroll
    for (int k = 0; k < 7; k++) a[k] = ea[e * 7 + k];
    float e0 = __ldg(&be1[0]), e1 = __ldg(&be1[1]);
#pragma unroll
    for (int k = 0; k < 7; k++) {
        e0 += a[k] * __ldg(&We1[k * 2 + 0]);
        e1 += a[k] * __ldg(&We1[k * 2 + 1]);
    }
    int s = g_src[e], d = g_dst[e];
    float m0 = fmaxf(x[2 * s + 0] + e0, 0.f);
    float m1 = fmaxf(x[2 * s + 1] + e1, 0.f);
    red_add_v2(((float*)g_agb) + 2 * d, m0, m1);
}

// ---------------- layer 1 nn: h = relu((x + aggr) @ W1 + b1) ----------------
__global__ void k_layer1nn(const float* __restrict__ x,
                           const float* __restrict__ W1,
                           const float* __restrict__ b1) {
    int n = blockIdx.x;
    int c = threadIdx.x;
    const float* ag = (const float*)g_agb;
    float a0 = x[2 * n + 0] + ag[2 * n + 0];
    float a1 = x[2 * n + 1] + ag[2 * n + 1];
    float v = b1[c] + a0 * W1[c] + a1 * W1[HID + c];
    ((float*)g_hb)[n * HID + c] = fmaxf(v, 0.f);
}

// ---------------- layers 2/3 aggregation: CSR pull, one warp per node ------
// writes g_agb[d] = hin[d] + sum_{e into d} relu(hin[src] + We2^T ea[e] + be2)
__global__ void __launch_bounds__(256, 2)
k_aggr(int useHn, const float* __restrict__ ea,
       const float* __restrict__ We2, const float* __restrict__ be2) {
    const float* hin = useHn ? (const float*)g_hnb : (const float*)g_hb;
    float* outp = (float*)g_agb;
    int warp = (blockIdx.x * blockDim.x + threadIdx.x) >> 5;
    if (warp >= N_NODES) return;
    int lane = threadIdx.x & 31;
    int chA = lane * 4;
    int chB = 128 + lane * 4;

    float4 wA[7], wB[7];
#pragma unroll
    for (int k = 0; k < 7; k++) {
        wA[k] = *(const float4*)&We2[k * HID + chA];
        wB[k] = *(const float4*)&We2[k * HID + chB];
    }
    float4 bA = *(const float4*)&be2[chA];
    float4 bB = *(const float4*)&be2[chB];

    // self term
    float4 sA = *(const float4*)&hin[warp * HID + chA];
    float4 sB = *(const float4*)&hin[warp * HID + chB];

    int beg = g_rowptr[warp], end = g_rowptr[warp + 1];
    for (int j = beg; j < end; j++) {
        int2 se = g_csr[j];
        int s = se.x, e = se.y;
        float a[7];
#pragma unroll
        for (int k = 0; k < 7; k++) a[k] = __ldg(&ea[e * 7 + k]);
        float4 hA = *(const float4*)&hin[s * HID + chA];
        float4 hB = *(const float4*)&hin[s * HID + chB];
        float4 mA = bA, mB = bB;
#pragma unroll
        for (int k = 0; k < 7; k++) {
            mA.x += a[k] * wA[k].x; mA.y += a[k] * wA[k].y;
            mA.z += a[k] * wA[k].z; mA.w += a[k] * wA[k].w;
            mB.x += a[k] * wB[k].x; mB.y += a[k] * wB[k].y;
            mB.z += a[k] * wB[k].z; mB.w += a[k] * wB[k].w;
        }
        sA.x += fmaxf(mA.x + hA.x, 0.f); sA.y += fmaxf(mA.y + hA.y, 0.f);
        sA.z += fmaxf(mA.z + hA.z, 0.f); sA.w += fmaxf(mA.w + hA.w, 0.f);
        sB.x += fmaxf(mB.x + hB.x, 0.f); sB.y += fmaxf(mB.y + hB.y, 0.f);
        sB.z += fmaxf(mB.z + hB.z, 0.f); sB.w += fmaxf(mB.w + hB.w, 0.f);
    }
    *(float4*)&outp[warp * HID + chA] = sA;
    *(float4*)&outp[warp * HID + chB] = sB;
}

// ---------------- GEMM: hout = relu(g_agb @ W + b) ----------------
// M=50000, N=256, K=256. BM=128, BN=128, BK=16, 256 threads, 8x8/thread.
#define BM 128
#define BN 128
#define BK 16
__global__ void __launch_bounds__(256)
k_gemm_relu(int layer, const float* __restrict__ W, const float* __restrict__ b) {
    const float* A = (const float*)g_agb;
    float* hout = (layer == 2) ? (float*)g_hnb : (float*)g_hb;

    __shared__ float As[BK][BM + 4];   // transposed A tile
    __shared__ float Bs[BK][BN];

    int tid = threadIdx.x;
    int tx = tid & 15, ty = tid >> 4;
    int rowBase = blockIdx.y * BM;
    int colBase = blockIdx.x * BN;

    float acc[8][8];
#pragma unroll
    for (int i = 0; i < 8; i++)
#pragma unroll
        for (int j = 0; j < 8; j++) acc[i][j] = 0.f;

    for (int kt = 0; kt < HID; kt += BK) {
        // load A tile (128 rows x 16 k), store transposed
        {
            int r = tid >> 1, c0 = (tid & 1) * 8;
            int grow = rowBase + r;
            float4 a0 = make_float4(0.f, 0.f, 0.f, 0.f), a1 = a0;
            if (grow < N_NODES) {
                a0 = *(const float4*)&A[grow * HID + kt + c0];
                a1 = *(const float4*)&A[grow * HID + kt + c0 + 4];
            }
            As[c0 + 0][r] = a0.x; As[c0 + 1][r] = a0.y;
            As[c0 + 2][r] = a0.z; As[c0 + 3][r] = a0.w;
            As[c0 + 4][r] = a1.x; As[c0 + 5][r] = a1.y;
            As[c0 + 6][r] = a1.z; As[c0 + 7][r] = a1.w;
        }
        // load B tile (16 k x 128 cols)
        {
            int br = tid >> 4, bc = (tid & 15) * 8;
            float4 b0 = *(const float4*)&W[(kt + br) * HID + colBase + bc];
            float4 b1 = *(const float4*)&W[(kt + br) * HID + colBase + bc + 4];
            *(float4*)&Bs[br][bc] = b0;
            *(float4*)&Bs[br][bc + 4] = b1;
        }
        __syncthreads();
#pragma unroll
        for (int k = 0; k < BK; k++) {
            float av[8], bv[8];
            *(float4*)av       = *(const float4*)&As[k][ty * 8];
            *(float4*)(av + 4) = *(const float4*)&As[k][ty * 8 + 4];
            *(float4*)bv       = *(const float4*)&Bs[k][tx * 8];
            *(float4*)(bv + 4) = *(const float4*)&Bs[k][tx * 8 + 4];
#pragma unroll
            for (int i = 0; i < 8; i++)
#pragma unroll
                for (int j = 0; j < 8; j++) acc[i][j] += av[i] * bv[j];
        }
        __syncthreads();
    }

#pragma unroll
    for (int i = 0; i < 8; i++) {
        int grow = rowBase + ty * 8 + i;
        if (grow >= N_NODES) continue;
#pragma unroll
        for (int j = 0; j < 8; j += 4) {
            int col = colBase + tx * 8 + j;
            float4 v;
            v.x = fmaxf(acc[i][j + 0] + b[col + 0], 0.f);
            v.y = fmaxf(acc[i][j + 1] + b[col + 1], 0.f);
            v.z = fmaxf(acc[i][j + 2] + b[col + 2], 0.f);
            v.w = fmaxf(acc[i][j + 3] + b[col + 3], 0.f);
            *(float4*)&hout[grow * HID + col] = v;
        }
    }
}

// ---------------- final: sigmoid(h @ Wend + bend) ----------------
__global__ void k_final(const float* __restrict__ Wend,
                        const float* __restrict__ bend,
                        float* __restrict__ out) {
    int lane = threadIdx.x & 31;
    int warp = threadIdx.x >> 5;
    int n = blockIdx.x * 8 + warp;
    if (n >= N_NODES) return;
    const float* h = (const float*)g_hb;
    float s = 0.f;
#pragma unroll
    for (int c = lane * 4; c < HID; c += 128) {
        float4 hv = *(const float4*)&h[n * HID + c];
        float4 wv = *(const float4*)&Wend[c];
        s += hv.x * wv.x + hv.y * wv.y + hv.z * wv.z + hv.w * wv.w;
    }
#pragma unroll
    for (int o = 16; o; o >>= 1) s += __shfl_xor_sync(0xffffffffu, s, o);
    if (lane == 0) out[n] = 1.f / (1.f + __expf(-(s + bend[0])));
}

// ---------------- host ----------------
extern "C" void kernel_launch(void* const* d_in, const int* in_sizes, int n_in,
                              void* d_out, int out_size) {
    const float* x    = (const float*)d_in[0];
    const void*  ei   = d_in[1];
    const float* ea   = (const float*)d_in[2];
    const float* We1  = (const float*)d_in[3];
    const float* be1  = (const float*)d_in[4];
    const float* W1   = (const float*)d_in[5];
    const float* b1   = (const float*)d_in[6];
    const float* We2  = (const float*)d_in[7];
    const float* be2  = (const float*)d_in[8];
    const float* W2   = (const float*)d_in[9];
    const float* b2   = (const float*)d_in[10];
    const float* Wend = (const float*)d_in[11];
    const float* bend = (const float*)d_in[12];
    float* out = (float*)d_out;

    void *p_deg = nullptr, *p_agb = nullptr;
    cudaGetSymbolAddress(&p_deg, g_deg);
    cudaGetSymbolAddress(&p_agb, g_agb);

    k_detect<<<1, 32>>>(ei);
    k_convert<<<(N_EDGES + 255) / 256, 256>>>(ei);

    // CSR build (by dst)
    cudaMemsetAsync(p_deg, 0, N_NODES * sizeof(int));
    k_hist<<<(N_EDGES + 255) / 256, 256>>>();
    k_scan<<<1, 1024>>>();
    k_fill<<<(N_EDGES + 255) / 256, 256>>>();

    // layer 1 (aggr in first 2*N floats of g_agb)
    cudaMemsetAsync(p_agb, 0, N_NODES * 2 * sizeof(float));
    k_scatter1<<<(N_EDGES + 255) / 256, 256>>>(x, ea, We1, be1);
    k_layer1nn<<<N_NODES, 256>>>(x, W1, b1);

    // layer 2: pull-aggregate from g_hb, GEMM -> g_hnb
    k_aggr<<<(N_NODES * 32 + 255) / 256, 256>>>(0, ea, We2, be2);
    k_gemm_relu<<<dim3(2, (N_NODES + BM - 1) / BM), 256>>>(2, W2, b2);

    // layer 3: pull-aggregate from g_hnb, GEMM -> g_hb
    k_aggr<<<(N_NODES * 32 + 255) / 256, 256>>>(1, ea, We2, be2);
    k_gemm_relu<<<dim3(2, (N_NODES + BM - 1) / BM), 256>>>(3, W2, b2);

    k_final<<<(N_NODES + 7) / 8, 256>>>(Wend, bend, out);
}

// round 4
// speedup vs baseline: 1.4337x; 1.3089x over previous
#include <cuda_runtime.h>

#define N_NODES 50000
#define N_EDGES 1600000
#define HID 256
#define SCAN_B 196   // ceil(N_NODES/256)

// ---------------- device scratch (static, no allocs) ----------------
__device__ float4 g_hb [N_NODES*HID/4];   // h buffer A
__device__ float4 g_hnb[N_NODES*HID/4];   // h buffer B
__device__ float4 g_agb[N_NODES*HID/4];   // (h_self + aggr) buffer / layer1 aggr
__device__ int    g_src[N_EDGES];
__device__ int    g_dst[N_EDGES];
__device__ int    g_deg[N_NODES];
__device__ int    g_rowptr[N_NODES + 1];
__device__ int    g_cur[N_NODES];
__device__ int    g_csrs[N_EDGES];        // src node, grouped by dst
__device__ float4 g_eas[N_EDGES * 2];     // edge attrs (7 + pad) in CSR order
__device__ int    g_bsum[SCAN_B];
__device__ int    g_boff[SCAN_B];
__device__ int    g_flag;                 // 1 = edge_index int64, 0 = int32

__device__ __forceinline__ void red_add_v2(float* a, float x, float y) {
    asm volatile("red.global.add.v2.f32 [%0], {%1,%2};"
                 :: "l"(a), "f"(x), "f"(y) : "memory");
}

// ---------------- dtype detection + index conversion ----------------
__global__ void k_detect(const void* ei) {
    if (threadIdx.x == 0) {
        const long long* p = (const long long*)ei;
        int is64 = 1;
        for (int i = 0; i < 64; i++) {
            long long v = p[i];
            if (v < 0 || v >= N_NODES) { is64 = 0; break; }
        }
        g_flag = is64;
    }
}

__global__ void k_convert(const void* ei) {
    int i = blockIdx.x * blockDim.x + threadIdx.x;
    if (i >= N_EDGES) return;
    if (g_flag) {
        const long long* p = (const long long*)ei;
        g_src[i] = (int)p[i];
        g_dst[i] = (int)p[N_EDGES + i];
    } else {
        const int* p = (const int*)ei;
        g_src[i] = p[i];
        g_dst[i] = p[N_EDGES + i];
    }
}

// ---------------- CSR build ----------------
__global__ void k_hist() {
    int i = blockIdx.x * blockDim.x + threadIdx.x;
    if (i < N_EDGES) atomicAdd(&g_deg[g_dst[i]], 1);
}

// block partial sums of degree
__global__ void k_part() {
    __shared__ int sm[256];
    int t = threadIdx.x;
    int n = blockIdx.x * 256 + t;
    int v = (n < N_NODES) ? g_deg[n] : 0;
    sm[t] = v;
    __syncthreads();
    for (int o = 128; o; o >>= 1) {
        if (t < o) sm[t] += sm[t + o];
        __syncthreads();
    }
    if (t == 0) g_bsum[blockIdx.x] = sm[0];
}

// single block scans SCAN_B partials -> exclusive block offsets
__global__ void k_scanb() {
    __shared__ int sm[256];
    int t = threadIdx.x;
    int v = (t < SCAN_B) ? g_bsum[t] : 0;
    sm[t] = v;
    __syncthreads();
    for (int o = 1; o < 256; o <<= 1) {
        int u = (t >= o) ? sm[t - o] : 0;
        __syncthreads();
        sm[t] += u;
        __syncthreads();
    }
    if (t < SCAN_B) g_boff[t] = sm[t] - v;   // exclusive
    if (t == 0) g_rowptr[N_NODES] = N_EDGES;
}

// per-block exclusive scan of degrees + block offset -> rowptr, cur
__global__ void k_rowptr() {
    __shared__ int sm[256];
    int t = threadIdx.x;
    int n = blockIdx.x * 256 + t;
    int v = (n < N_NODES) ? g_deg[n] : 0;
    sm[t] = v;
    __syncthreads();
    for (int o = 1; o < 256; o <<= 1) {
        int u = (t >= o) ? sm[t - o] : 0;
        __syncthreads();
        sm[t] += u;
        __syncthreads();
    }
    if (n < N_NODES) {
        int r = g_boff[blockIdx.x] + sm[t] - v;
        g_rowptr[n] = r;
        g_cur[n] = r;
    }
}

// fill CSR: src ids + edge attrs reordered into CSR order (padded float4 x2)
__global__ void k_fill(const float* __restrict__ ea) {
    int e = blockIdx.x * blockDim.x + threadIdx.x;
    if (e >= N_EDGES) return;
    int d = g_dst[e];
    int pos = atomicAdd(&g_cur[d], 1);
    g_csrs[pos] = g_src[e];
    const float* a = ea + (size_t)e * 7;
    float4 v0 = make_float4(a[0], a[1], a[2], a[3]);
    float4 v1 = make_float4(a[4], a[5], a[6], 0.f);
    g_eas[pos * 2 + 0] = v0;
    g_eas[pos * 2 + 1] = v1;
}

// ---------------- layer 1 scatter (C = 2, atomic push) ----------------
__global__ void k_scatter1(const float* __restrict__ x,
                           const float* __restrict__ ea,
                           const float* __restrict__ We1,
                           const float* __restrict__ be1) {
    int e = blockIdx.x * blockDim.x + threadIdx.x;
    if (e >= N_EDGES) return;
    float a[7];
#pragma unroll
    for (int k = 0; k < 7; k++) a[k] = ea[e * 7 + k];
    float e0 = __ldg(&be1[0]), e1 = __ldg(&be1[1]);
#pragma unroll
    for (int k = 0; k < 7; k++) {
        e0 += a[k] * __ldg(&We1[k * 2 + 0]);
        e1 += a[k] * __ldg(&We1[k * 2 + 1]);
    }
    int s = g_src[e], d = g_dst[e];
    float m0 = fmaxf(x[2 * s + 0] + e0, 0.f);
    float m1 = fmaxf(x[2 * s + 1] + e1, 0.f);
    red_add_v2(((float*)g_agb) + 2 * d, m0, m1);
}

// ---------------- layer 1 nn: h = relu((x + aggr) @ W1 + b1) ----------------
__global__ void k_layer1nn(const float* __restrict__ x,
                           const float* __restrict__ W1,
                           const float* __restrict__ b1) {
    int n = blockIdx.x;
    int c = threadIdx.x;
    const float* ag = (const float*)g_agb;
    float a0 = x[2 * n + 0] + ag[2 * n + 0];
    float a1 = x[2 * n + 1] + ag[2 * n + 1];
    float v = b1[c] + a0 * W1[c] + a1 * W1[HID + c];
    ((float*)g_hb)[n * HID + c] = fmaxf(v, 0.f);
}

// ---------------- layers 2/3 aggregation: CSR pull ----------------
// 2 warps per node, each warp owns 128 channels. Edges processed in batches
// of 4 for memory-level parallelism.
__device__ __forceinline__ void aggr_step(
    float4& acc, const float4* w, float4 bb,
    float4 a0, float4 a1, float4 h)
{
    float4 m = bb;
    m.x += a0.x * w[0].x; m.y += a0.x * w[0].y; m.z += a0.x * w[0].z; m.w += a0.x * w[0].w;
    m.x += a0.y * w[1].x; m.y += a0.y * w[1].y; m.z += a0.y * w[1].z; m.w += a0.y * w[1].w;
    m.x += a0.z * w[2].x; m.y += a0.z * w[2].y; m.z += a0.z * w[2].z; m.w += a0.z * w[2].w;
    m.x += a0.w * w[3].x; m.y += a0.w * w[3].y; m.z += a0.w * w[3].z; m.w += a0.w * w[3].w;
    m.x += a1.x * w[4].x; m.y += a1.x * w[4].y; m.z += a1.x * w[4].z; m.w += a1.x * w[4].w;
    m.x += a1.y * w[5].x; m.y += a1.y * w[5].y; m.z += a1.y * w[5].z; m.w += a1.y * w[5].w;
    m.x += a1.z * w[6].x; m.y += a1.z * w[6].y; m.z += a1.z * w[6].z; m.w += a1.z * w[6].w;
    acc.x += fmaxf(m.x + h.x, 0.f);
    acc.y += fmaxf(m.y + h.y, 0.f);
    acc.z += fmaxf(m.z + h.z, 0.f);
    acc.w += fmaxf(m.w + h.w, 0.f);
}

__global__ void __launch_bounds__(256)
k_aggr(int useHn, const float* __restrict__ We2, const float* __restrict__ be2) {
    const float* hin = useHn ? (const float*)g_hnb : (const float*)g_hb;
    float* outp = (float*)g_agb;
    int gw = (blockIdx.x * blockDim.x + threadIdx.x) >> 5;
    int node = gw >> 1;
    if (node >= N_NODES) return;
    int half = gw & 1;
    int lane = threadIdx.x & 31;
    int ch = half * 128 + lane * 4;

    float4 w[7];
#pragma unroll
    for (int k = 0; k < 7; k++) w[k] = *(const float4*)&We2[k * HID + ch];
    float4 bb = *(const float4*)&be2[ch];

    float4 acc = *(const float4*)&hin[node * HID + ch];   // self term

    int beg = g_rowptr[node], end = g_rowptr[node + 1];
    int j = beg;
    for (; j + 4 <= end; j += 4) {
        int s0 = g_csrs[j], s1 = g_csrs[j + 1], s2 = g_csrs[j + 2], s3 = g_csrs[j + 3];
        float4 e00 = g_eas[(j + 0) * 2], e01 = g_eas[(j + 0) * 2 + 1];
        float4 e10 = g_eas[(j + 1) * 2], e11 = g_eas[(j + 1) * 2 + 1];
        float4 e20 = g_eas[(j + 2) * 2], e21 = g_eas[(j + 2) * 2 + 1];
        float4 e30 = g_eas[(j + 3) * 2], e31 = g_eas[(j + 3) * 2 + 1];
        float4 h0 = *(const float4*)&hin[s0 * HID + ch];
        float4 h1 = *(const float4*)&hin[s1 * HID + ch];
        float4 h2 = *(const float4*)&hin[s2 * HID + ch];
        float4 h3 = *(const float4*)&hin[s3 * HID + ch];
        aggr_step(acc, w, bb, e00, e01, h0);
        aggr_step(acc, w, bb, e10, e11, h1);
        aggr_step(acc, w, bb, e20, e21, h2);
        aggr_step(acc, w, bb, e30, e31, h3);
    }
    for (; j < end; j++) {
        int s = g_csrs[j];
        float4 a0 = g_eas[j * 2], a1 = g_eas[j * 2 + 1];
        float4 h = *(const float4*)&hin[s * HID + ch];
        aggr_step(acc, w, bb, a0, a1, h);
    }
    *(float4*)&outp[node * HID + ch] = acc;
}

// ---------------- GEMM: hout = relu(g_agb @ W + b) ----------------
// M=50000, N=256, K=256. BM=128, BN=128, BK=16, 256 threads, 8x8/thread.
#define BM 128
#define BN 128
#define BK 16
__global__ void __launch_bounds__(256)
k_gemm_relu(int layer, const float* __restrict__ W, const float* __restrict__ b) {
    const float* A = (const float*)g_agb;
    float* hout = (layer == 2) ? (float*)g_hnb : (float*)g_hb;

    __shared__ float As[BK][BM + 4];   // transposed A tile
    __shared__ float Bs[BK][BN];

    int tid = threadIdx.x;
    int tx = tid & 15, ty = tid >> 4;
    int rowBase = blockIdx.y * BM;
    int colBase = blockIdx.x * BN;

    float acc[8][8];
#pragma unroll
    for (int i = 0; i < 8; i++)
#pragma unroll
        for (int j = 0; j < 8; j++) acc[i][j] = 0.f;

    for (int kt = 0; kt < HID; kt += BK) {
        {
            int r = tid >> 1, c0 = (tid & 1) * 8;
            int grow = rowBase + r;
            float4 a0 = make_float4(0.f, 0.f, 0.f, 0.f), a1 = a0;
            if (grow < N_NODES) {
                a0 = *(const float4*)&A[grow * HID + kt + c0];
                a1 = *(const float4*)&A[grow * HID + kt + c0 + 4];
            }
            As[c0 + 0][r] = a0.x; As[c0 + 1][r] = a0.y;
            As[c0 + 2][r] = a0.z; As[c0 + 3][r] = a0.w;
            As[c0 + 4][r] = a1.x; As[c0 + 5][r] = a1.y;
            As[c0 + 6][r] = a1.z; As[c0 + 7][r] = a1.w;
        }
        {
            int br = tid >> 4, bc = (tid & 15) * 8;
            float4 b0 = *(const float4*)&W[(kt + br) * HID + colBase + bc];
            float4 b1 = *(const float4*)&W[(kt + br) * HID + colBase + bc + 4];
            *(float4*)&Bs[br][bc] = b0;
            *(float4*)&Bs[br][bc + 4] = b1;
        }
        __syncthreads();
#pragma unroll
        for (int k = 0; k < BK; k++) {
            float av[8], bv[8];
            *(float4*)av       = *(const float4*)&As[k][ty * 8];
            *(float4*)(av + 4) = *(const float4*)&As[k][ty * 8 + 4];
            *(float4*)bv       = *(const float4*)&Bs[k][tx * 8];
            *(float4*)(bv + 4) = *(const float4*)&Bs[k][tx * 8 + 4];
#pragma unroll
            for (int i = 0; i < 8; i++)
#pragma unroll
                for (int j = 0; j < 8; j++) acc[i][j] += av[i] * bv[j];
        }
        __syncthreads();
    }

#pragma unroll
    for (int i = 0; i < 8; i++) {
        int grow = rowBase + ty * 8 + i;
        if (grow >= N_NODES) continue;
#pragma unroll
        for (int j = 0; j < 8; j += 4) {
            int col = colBase + tx * 8 + j;
            float4 v;
            v.x = fmaxf(acc[i][j + 0] + b[col + 0], 0.f);
            v.y = fmaxf(acc[i][j + 1] + b[col + 1], 0.f);
            v.z = fmaxf(acc[i][j + 2] + b[col + 2], 0.f);
            v.w = fmaxf(acc[i][j + 3] + b[col + 3], 0.f);
            *(float4*)&hout[grow * HID + col] = v;
        }
    }
}

// ---------------- final: sigmoid(h @ Wend + bend) ----------------
__global__ void k_final(const float* __restrict__ Wend,
                        const float* __restrict__ bend,
                        float* __restrict__ out) {
    int lane = threadIdx.x & 31;
    int warp = threadIdx.x >> 5;
    int n = blockIdx.x * 8 + warp;
    if (n >= N_NODES) return;
    const float* h = (const float*)g_hb;
    float s = 0.f;
#pragma unroll
    for (int c = lane * 4; c < HID; c += 128) {
        float4 hv = *(const float4*)&h[n * HID + c];
        float4 wv = *(const float4*)&Wend[c];
        s += hv.x * wv.x + hv.y * wv.y + hv.z * wv.z + hv.w * wv.w;
    }
#pragma unroll
    for (int o = 16; o; o >>= 1) s += __shfl_xor_sync(0xffffffffu, s, o);
    if (lane == 0) out[n] = 1.f / (1.f + __expf(-(s + bend[0])));
}

// ---------------- host ----------------
extern "C" void kernel_launch(void* const* d_in, const int* in_sizes, int n_in,
                              void* d_out, int out_size) {
    const float* x    = (const float*)d_in[0];
    const void*  ei   = d_in[1];
    const float* ea   = (const float*)d_in[2];
    const float* We1  = (const float*)d_in[3];
    const float* be1  = (const float*)d_in[4];
    const float* W1   = (const float*)d_in[5];
    const float* b1   = (const float*)d_in[6];
    const float* We2  = (const float*)d_in[7];
    const float* be2  = (const float*)d_in[8];
    const float* W2   = (const float*)d_in[9];
    const float* b2   = (const float*)d_in[10];
    const float* Wend = (const float*)d_in[11];
    const float* bend = (const float*)d_in[12];
    float* out = (float*)d_out;

    void *p_deg = nullptr, *p_agb = nullptr;
    cudaGetSymbolAddress(&p_deg, g_deg);
    cudaGetSymbolAddress(&p_agb, g_agb);

    k_detect<<<1, 32>>>(ei);
    k_convert<<<(N_EDGES + 255) / 256, 256>>>(ei);

    // CSR build (by dst)
    cudaMemsetAsync(p_deg, 0, N_NODES * sizeof(int));
    k_hist<<<(N_EDGES + 255) / 256, 256>>>();
    k_part<<<SCAN_B, 256>>>();
    k_scanb<<<1, 256>>>();
    k_rowptr<<<SCAN_B, 256>>>();
    k_fill<<<(N_EDGES + 255) / 256, 256>>>(ea);

    // layer 1 (aggr in first 2*N floats of g_agb)
    cudaMemsetAsync(p_agb, 0, N_NODES * 2 * sizeof(float));
    k_scatter1<<<(N_EDGES + 255) / 256, 256>>>(x, ea, We1, be1);
    k_layer1nn<<<N_NODES, 256>>>(x, W1, b1);

    // layer 2: pull-aggregate from g_hb, GEMM -> g_hnb
    k_aggr<<<(N_NODES * 2 * 32 + 255) / 256, 256>>>(0, We2, be2);
    k_gemm_relu<<<dim3(2, (N_NODES + BM - 1) / BM), 256>>>(2, W2, b2);

    // layer 3: pull-aggregate from g_hnb, GEMM -> g_hb
    k_aggr<<<(N_NODES * 2 * 32 + 255) / 256, 256>>>(1, We2, be2);
    k_gemm_relu<<<dim3(2, (N_NODES + BM - 1) / BM), 256>>>(3, W2, b2);

    k_final<<<(N_NODES + 7) / 8, 256>>>(Wend, bend, out);
}